// round 3
// baseline (speedup 1.0000x reference)
#include <cuda_runtime.h>
#include <math_constants.h>

#define B_ 32
#define H_ 8
#define L_ 2048
#define E_ 64

#define NTHREADS 256
#define ROWS 32          // rows (l positions) per block
#define RP   16          // row-pairs per block

// packed f32x2 fma: d = a*b + d (elementwise on packed float2 in a 64-bit reg)
__device__ __forceinline__ void ffma2(unsigned long long& d,
                                      unsigned long long a,
                                      unsigned long long b) {
    asm("fma.rn.f32x2 %0, %1, %2, %0;" : "+l"(d) : "l"(a), "l"(b));
}

// AutoCorrelation (Autoformer):
//   corr[b,h,l,d] = sum_e q[b,h,l,(e+d)%64] * k[b,h,l,e]
//   top-4 over d, softmax, V_out[e] = sum_i p_i * v[(e+d_i)%64]
//   outputs: V (B,H,L,E) then corr transposed to (B,E,H,L)
__global__ __launch_bounds__(NTHREADS, 4)
void ac_kernel(const float* __restrict__ Q, const float* __restrict__ Kk,
               const float* __restrict__ Vv, float* __restrict__ outV,
               float* __restrict__ outC)
{
    // s_qq: per row-pair, 128 interleaved pairs (q duplicated to avoid wrap),
    //       stored as swizzled 16B chunks: chunk c at position c ^ ((c>>3)&1)
    __shared__ __align__(16) float s_qq[RP][256];
    __shared__ __align__(16) float s_kk[RP][128];   // 64 interleaved pairs
    __shared__ float s_v[ROWS][66];
    __shared__ float s_c[ROWS][67];

    const int t     = threadIdx.x;
    const int ltile = blockIdx.x;
    const int bh    = blockIdx.y;
    const int h     = bh & (H_ - 1);
    const int b     = bh >> 3;
    const int l0    = ltile * ROWS;

    // ---------------- load + interleave (warp loads exactly its own rows) ----
    {
        const int r   = t >> 3;          // block-local row 0..31
        const int g   = t & 7;           // 8 threads per row
        const int rp  = r >> 1;
        const int par = r & 1;
        const size_t rowbase = ((size_t)bh * L_ + l0 + r) * E_;
        const int col = 8 * g;

        float4 q0 = *(const float4*)(Q  + rowbase + col);
        float4 q1 = *(const float4*)(Q  + rowbase + col + 4);
        float4 k0 = *(const float4*)(Kk + rowbase + col);
        float4 k1 = *(const float4*)(Kk + rowbase + col + 4);
        float4 v0 = *(const float4*)(Vv + rowbase + col);
        float4 v1 = *(const float4*)(Vv + rowbase + col + 4);

        float qf[8] = {q0.x,q0.y,q0.z,q0.w,q1.x,q1.y,q1.z,q1.w};
        float kf[8] = {k0.x,k0.y,k0.z,k0.w,k1.x,k1.y,k1.z,k1.w};
        float vf[8] = {v0.x,v0.y,v0.z,v0.w,v1.x,v1.y,v1.z,v1.w};

        #pragma unroll
        for (int u = 0; u < 8; ++u) {
            int i  = col + u;
            // q (original + duplicate at +64), swizzled interleaved
            int c0  = i >> 1;
            int p0  = c0 ^ ((c0 >> 3) & 1);
            s_qq[rp][p0 * 4 + (i & 1) * 2 + par] = qf[u];
            int i2  = i + 64;
            int c2  = i2 >> 1;
            int p2  = c2 ^ ((c2 >> 3) & 1);
            s_qq[rp][p2 * 4 + (i2 & 1) * 2 + par] = qf[u];
            // k interleaved (no swizzle: broadcast reads)
            s_kk[rp][i * 2 + par] = kf[u];
            // v plain
            s_v[r][i] = vf[u];
        }
    }
    __syncwarp();

    // ---------------- correlation: FIR window + f32x2, 2 rows per lane -------
    const int lane = t & 31;
    const int sub  = lane & 15;
    const int half = lane >> 4;
    const int w    = t >> 5;
    const int rp   = 2 * w + half;      // row-pair handled by this half-warp
    const int d0   = 4 * sub;           // this lane's 4 delays: d0..d0+3

    const float* qq = s_qq[rp];
    const float* kk = s_kk[rp];

    #define LDQ(c) (*(const ulonglong2*)(qq + 4 * ((c) ^ (((c) >> 3) & 1))))
    #define LDK(c) (*(const ulonglong2*)(kk + 4 * (c)))

    unsigned long long Wr[8];
    {
        ulonglong2 t0 = LDQ(d0 >> 1);       Wr[0] = t0.x; Wr[1] = t0.y;
        ulonglong2 t1 = LDQ((d0 >> 1) + 1); Wr[2] = t1.x; Wr[3] = t1.y;
    }
    unsigned long long acc[4] = {0ull, 0ull, 0ull, 0ull};

    #pragma unroll
    for (int blk = 0; blk < 16; ++blk) {
        const int e0 = blk * 4;
        const int cb = (e0 + d0) >> 1;
        ulonglong2 t0 = LDQ(cb + 2); Wr[4] = t0.x; Wr[5] = t0.y;
        ulonglong2 t1 = LDQ(cb + 3); Wr[6] = t1.x; Wr[7] = t1.y;
        ulonglong2 ka = LDK(e0 >> 1), kb = LDK((e0 >> 1) + 1);
        unsigned long long kp[4] = {ka.x, ka.y, kb.x, kb.y};
        #pragma unroll
        for (int tt = 0; tt < 4; ++tt)
            #pragma unroll
            for (int j = 0; j < 4; ++j)
                ffma2(acc[j], Wr[tt + j], kp[tt]);
        Wr[0] = Wr[4]; Wr[1] = Wr[5]; Wr[2] = Wr[6]; Wr[3] = Wr[7];
    }

    // unpack + stage corr for the transposed output
    float cx[4], cy[4];
    #pragma unroll
    for (int j = 0; j < 4; ++j) {
        float2 f2 = *reinterpret_cast<float2*>(&acc[j]);
        cx[j] = f2.x; cy[j] = f2.y;
        s_c[2 * rp][d0 + j]     = f2.x;
        s_c[2 * rp + 1][d0 + j] = f2.y;
    }

    // ---------------- top-4 + softmax + delay aggregation (2 passes) --------
    #pragma unroll
    for (int pass = 0; pass < 2; ++pass) {
        const int row = 2 * rp + pass;
        float a0 = pass ? cy[0] : cx[0];
        float a1 = pass ? cy[1] : cx[1];
        float a2 = pass ? cy[2] : cx[2];
        float a3 = pass ? cy[3] : cx[3];

        float wv[4]; int wd[4];
        #pragma unroll
        for (int i = 0; i < 4; ++i) {
            // local argmax, lowest index wins on ties
            float bv = a0; int bj = 0;
            if (a1 > bv) { bv = a1; bj = 1; }
            if (a2 > bv) { bv = a2; bj = 2; }
            if (a3 > bv) { bv = a3; bj = 3; }
            int bi = d0 + bj;
            // 16-lane butterfly (stays within half-warp), lexicographic
            #pragma unroll
            for (int off = 8; off; off >>= 1) {
                float ov = __shfl_xor_sync(0xffffffffu, bv, off);
                int   oi = __shfl_xor_sync(0xffffffffu, bi, off);
                if (ov > bv || (ov == bv && oi < bi)) { bv = ov; bi = oi; }
            }
            wv[i] = bv; wd[i] = bi;
            int loc = bi - d0;               // remove if ours
            if (loc == 0) a0 = -CUDART_INF_F;
            if (loc == 1) a1 = -CUDART_INF_F;
            if (loc == 2) a2 = -CUDART_INF_F;
            if (loc == 3) a3 = -CUDART_INF_F;
        }

        float p[4]; float z = 0.f;
        #pragma unroll
        for (int i = 0; i < 4; ++i) { p[i] = __expf(wv[i] - wv[0]); z += p[i]; }
        const float rz = 1.f / z;

        const float* vd = s_v[row];
        float o0 = 0.f, o1 = 0.f, o2 = 0.f, o3 = 0.f;
        #pragma unroll
        for (int i = 0; i < 4; ++i) {
            float pi = p[i] * rz;
            int base = d0 + wd[i];
            o0 = fmaf(pi, vd[(base + 0) & 63], o0);
            o1 = fmaf(pi, vd[(base + 1) & 63], o1);
            o2 = fmaf(pi, vd[(base + 2) & 63], o2);
            o3 = fmaf(pi, vd[(base + 3) & 63], o3);
        }
        const size_t vbase = ((size_t)bh * L_ + l0 + row) * E_;
        *(float4*)(outV + vbase + d0) = make_float4(o0, o1, o2, o3);
    }

    // ---------------- transposed corr write: outC[b,e,h,l] -------------------
    __syncthreads();
    #pragma unroll
    for (int idx = t; idx < E_ * ROWS; idx += NTHREADS) {
        int e = idx >> 5;            // ROWS == 32
        int r = idx & 31;
        outC[(((size_t)b * E_ + e) * H_ + h) * (size_t)L_ + l0 + r] = s_c[r][e];
    }
}

extern "C" void kernel_launch(void* const* d_in, const int* in_sizes, int n_in,
                              void* d_out, int out_size)
{
    const float* Q = (const float*)d_in[0];
    const float* K = (const float*)d_in[1];
    const float* V = (const float*)d_in[2];
    float* outV = (float*)d_out;
    float* outC = outV + (size_t)B_ * H_ * L_ * E_;

    dim3 grid(L_ / ROWS, B_ * H_);
    ac_kernel<<<grid, NTHREADS>>>(Q, K, V, outV, outC);
}

// round 4
// speedup vs baseline: 1.0333x; 1.0333x over previous
#include <cuda_runtime.h>
#include <math_constants.h>

#define B_ 32
#define H_ 8
#define L_ 2048
#define E_ 64

#define NTHREADS 256
#define ROWS 32          // rows (l positions) per block
#define RP   16          // row-pairs per block

#define SQ 260           // s_qq row-pair stride in words (256 data + 4 quad-shift); corr aliases here
#define SK 128           // s_kk row-pair stride
#define SV 136           // s_v row stride (128 dup words; ≡8 mod 16 for cross-half deconflict)

// packed f32x2 fma: d = a*b + d
__device__ __forceinline__ void ffma2(unsigned long long& d,
                                      unsigned long long a,
                                      unsigned long long b) {
    asm("fma.rn.f32x2 %0, %1, %2, %0;" : "+l"(d) : "l"(a), "l"(b));
}

// AutoCorrelation (Autoformer):
//   corr[b,h,l,d] = sum_e q[b,h,l,(e+d)%64] * k[b,h,l,e]
//   top-4 over d, softmax, V_out[e] = sum_i p_i * v[(e+d_i)%64]
//   outputs: V (B,H,L,E) then corr transposed to (B,E,H,L)
__global__ __launch_bounds__(NTHREADS, 4)
void ac_kernel(const float* __restrict__ Q, const float* __restrict__ Kk,
               const float* __restrict__ Vv, float* __restrict__ outV,
               float* __restrict__ outC)
{
    // s_qq: per row-pair, 128 interleaved (even,odd) pairs (q duplicated; chunk-XOR swizzle).
    //       After the correlation loop, each rp's region is reused (aliased) to stage
    //       corr rows 2rp (words 0..65) and 2rp+1 (words 130..195).
    __shared__ __align__(16) float s_qq[RP * SQ];
    __shared__ __align__(16) float s_kk[RP * SK];
    __shared__ __align__(16) float s_v [ROWS * SV];   // v duplicated, parity-XOR4 word layout

    const int t     = threadIdx.x;
    const int lane  = t & 31;
    const int w     = t >> 5;
    const int ltile = blockIdx.x;
    const int bh    = blockIdx.y;
    const int h     = bh & (H_ - 1);
    const int b     = bh >> 3;
    const int l0    = ltile * ROWS;

    // ---------------- load phase: shuffle-built interleave, vector stores ----
    {
        const int g   = lane & 7;          // 8 col-groups of 8 floats
        const int rr  = lane >> 3;         // 4 local rows per warp
        const int par = rr & 1;
        const int rl  = 4 * w + rr;        // block-local row
        const int rpg = rl >> 1;           // row-pair index
        const size_t rowbase = ((size_t)bh * L_ + l0 + rl) * (size_t)E_;
        const int col = 8 * g;

        float4 q0 = *(const float4*)(Q  + rowbase + col);
        float4 q1 = *(const float4*)(Q  + rowbase + col + 4);
        float4 k0 = *(const float4*)(Kk + rowbase + col);
        float4 k1 = *(const float4*)(Kk + rowbase + col + 4);
        float4 v0 = *(const float4*)(Vv + rowbase + col);
        float4 v1 = *(const float4*)(Vv + rowbase + col + 4);

        // v: plain + duplicate, word i stored at (i ^ ((row&1)<<2))
        {
            const int x4 = (rl & 1) << 2;
            float* vr = s_v + rl * SV;
            *(float4*)(vr + ((col     ) ^ x4)) = v0;
            *(float4*)(vr + ((col +  4) ^ x4)) = v1;
            *(float4*)(vr + ((col + 64) ^ x4)) = v0;
            *(float4*)(vr + ((col + 68) ^ x4)) = v1;
        }

        // partner exchange (lane ^ 8 = other parity of same row-pair):
        // par0 sends its cols col+4..7, receives partner's col..col+3; par1 vice versa.
        float qs0 = par ? q0.x : q1.x, qs1 = par ? q0.y : q1.y,
              qs2 = par ? q0.z : q1.z, qs3 = par ? q0.w : q1.w;
        float ks0 = par ? k0.x : k1.x, ks1 = par ? k0.y : k1.y,
              ks2 = par ? k0.z : k1.z, ks3 = par ? k0.w : k1.w;
        float qr0 = __shfl_xor_sync(0xffffffffu, qs0, 8);
        float qr1 = __shfl_xor_sync(0xffffffffu, qs1, 8);
        float qr2 = __shfl_xor_sync(0xffffffffu, qs2, 8);
        float qr3 = __shfl_xor_sync(0xffffffffu, qs3, 8);
        float kr0 = __shfl_xor_sync(0xffffffffu, ks0, 8);
        float kr1 = __shfl_xor_sync(0xffffffffu, ks1, 8);
        float kr2 = __shfl_xor_sync(0xffffffffu, ks2, 8);
        float kr3 = __shfl_xor_sync(0xffffffffu, ks3, 8);

        float4 a0, a1, b0v, b1v;
        if (!par) {   // builds pairs for cols col..col+3: (my even val, partner odd val)
            a0  = make_float4(q0.x, qr0, q0.y, qr1);
            a1  = make_float4(q0.z, qr2, q0.w, qr3);
            b0v = make_float4(k0.x, kr0, k0.y, kr1);
            b1v = make_float4(k0.z, kr2, k0.w, kr3);
        } else {      // builds pairs for cols col+4..col+7: (partner even val, my odd val)
            a0  = make_float4(qr0, q1.x, qr1, q1.y);
            a1  = make_float4(qr2, q1.z, qr3, q1.w);
            b0v = make_float4(kr0, k1.x, kr1, k1.y);
            b1v = make_float4(kr2, k1.z, kr3, k1.w);
        }
        const int c0 = 4 * g + 2 * par;                  // logical chunk (2 pairs)
        const int p0 = c0 ^ ((c0 >> 3) & 1);             // swizzled chunk
        const int p1 = (c0 + 1) ^ (((c0 + 1) >> 3) & 1);
        float* qrow = s_qq + rpg * SQ;
        *(float4*)(qrow + 4 * p0) = a0;
        *(float4*)(qrow + 4 * p1) = a1;
        *(float4*)(qrow + 4 * p0 + 128) = a0;            // duplicate (+32 chunks)
        *(float4*)(qrow + 4 * p1 + 128) = a1;
        float* krow = s_kk + rpg * SK;
        *(float4*)(krow + 4 * c0)     = b0v;
        *(float4*)(krow + 4 * c0 + 4) = b1v;
    }
    __syncwarp();

    // ---------------- correlation: FIR window + f32x2, 2 rows per lane -------
    const int sub  = lane & 15;
    const int half = lane >> 4;
    const int rp   = 2 * w + half;      // row-pair handled by this half-warp
    const int d0   = 4 * sub;           // contiguous delays for the FIR window

    const float* qq = s_qq + rp * SQ;
    const float* kk = s_kk + rp * SK;

    #define LDQ(c) (*(const ulonglong2*)(qq + 4 * ((c) ^ (((c) >> 3) & 1))))
    #define LDK(c) (*(const ulonglong2*)(kk + 4 * (c)))

    unsigned long long Wr[8];
    {
        ulonglong2 t0 = LDQ(d0 >> 1);       Wr[0] = t0.x; Wr[1] = t0.y;
        ulonglong2 t1 = LDQ((d0 >> 1) + 1); Wr[2] = t1.x; Wr[3] = t1.y;
    }
    unsigned long long acc[4] = {0ull, 0ull, 0ull, 0ull};

    #pragma unroll
    for (int blk = 0; blk < 16; ++blk) {
        const int e0 = blk * 4;
        const int cb = (e0 + d0) >> 1;
        ulonglong2 t0 = LDQ(cb + 2); Wr[4] = t0.x; Wr[5] = t0.y;
        ulonglong2 t1 = LDQ(cb + 3); Wr[6] = t1.x; Wr[7] = t1.y;
        ulonglong2 ka = LDK(e0 >> 1), kb = LDK((e0 >> 1) + 1);
        unsigned long long kp[4] = {ka.x, ka.y, kb.x, kb.y};
        #pragma unroll
        for (int tt = 0; tt < 4; ++tt)
            #pragma unroll
            for (int j = 0; j < 4; ++j)
                ffma2(acc[j], Wr[tt + j], kp[tt]);
        Wr[0] = Wr[4]; Wr[1] = Wr[5]; Wr[2] = Wr[6]; Wr[3] = Wr[7];
    }
    __syncwarp();   // all q reads of this warp done before aliased corr staging

    // ---------------- stage corr into aliased q region (float2 pairs) --------
    {
        float2 f0 = *reinterpret_cast<float2*>(&acc[0]);
        float2 f1 = *reinterpret_cast<float2*>(&acc[1]);
        float2 f2 = *reinterpret_cast<float2*>(&acc[2]);
        float2 f3 = *reinterpret_cast<float2*>(&acc[3]);
        float* ce = s_qq + rp * SQ;          // corr row 2rp   : words 0..65
        float* co = ce + 130;                 // corr row 2rp+1 : words 130..195
        *(float2*)(ce + d0)     = make_float2(f0.x, f1.x);
        *(float2*)(ce + d0 + 2) = make_float2(f2.x, f3.x);
        *(float2*)(co + d0)     = make_float2(f0.y, f1.y);
        *(float2*)(co + d0 + 2) = make_float2(f2.y, f3.y);
    }
    __syncwarp();

    // ---------------- top-4 + softmax + aggregation (strided delays) ---------
    #pragma unroll
    for (int pass = 0; pass < 2; ++pass) {
        const int rowl = 2 * rp + pass;
        const float* crow = s_qq + rp * SQ + pass * 130;
        // lane's candidates: delays sub, sub+16, sub+32, sub+48 (conflict-free re-read)
        float a0c = crow[sub];
        float a1c = crow[sub + 16];
        float a2c = crow[sub + 32];
        float a3c = crow[sub + 48];

        float wv[4]; int wd[4];
        #pragma unroll
        for (int i = 0; i < 4; ++i) {
            // local argmax, lowest index (= lowest m) wins ties
            float bv = a0c; int bm = 0;
            if (a1c > bv) { bv = a1c; bm = 1; }
            if (a2c > bv) { bv = a2c; bm = 2; }
            if (a3c > bv) { bv = a3c; bm = 3; }
            int bi = sub + 16 * bm;
            #pragma unroll
            for (int off = 8; off; off >>= 1) {   // stays within the 16-lane half
                float ov = __shfl_xor_sync(0xffffffffu, bv, off);
                int   oi = __shfl_xor_sync(0xffffffffu, bi, off);
                if (ov > bv || (ov == bv && oi < bi)) { bv = ov; bi = oi; }
            }
            wv[i] = bv; wd[i] = bi;
            if ((bi & 15) == sub) {               // remove from owner lane
                int m = bi >> 4;
                if (m == 0) a0c = -CUDART_INF_F;
                if (m == 1) a1c = -CUDART_INF_F;
                if (m == 2) a2c = -CUDART_INF_F;
                if (m == 3) a3c = -CUDART_INF_F;
            }
        }

        float p[4]; float z = 0.f;
        #pragma unroll
        for (int i = 0; i < 4; ++i) { p[i] = __expf(wv[i] - wv[0]); z += p[i]; }
        const float rz = 1.f / z;

        // gather: idx = sub + 16m + wd[i] <= 126 (dup), word = idx ^ x4
        const float* vrow = s_v + rowl * SV;
        const int x4 = pass << 2;                 // (rowl & 1) << 2
        float o0 = 0.f, o1 = 0.f, o2 = 0.f, o3 = 0.f;
        #pragma unroll
        for (int i = 0; i < 4; ++i) {
            float pi = p[i] * rz;
            int bx = (sub + wd[i]) ^ x4;          // +16m commutes with ^4 (bit2 untouched)
            o0 = fmaf(pi, vrow[bx],      o0);
            o1 = fmaf(pi, vrow[bx + 16], o1);
            o2 = fmaf(pi, vrow[bx + 32], o2);
            o3 = fmaf(pi, vrow[bx + 48], o3);
        }
        const size_t vb = ((size_t)bh * L_ + l0 + rowl) * (size_t)E_;
        outV[vb + sub]      = o0;
        outV[vb + sub + 16] = o1;
        outV[vb + sub + 32] = o2;
        outV[vb + sub + 48] = o3;
    }

    // ---------------- transposed corr write: outC[b,e,h,l] -------------------
    __syncthreads();
    #pragma unroll
    for (int idx = t; idx < E_ * ROWS; idx += NTHREADS) {
        int e = idx >> 5;            // ROWS == 32
        int r = idx & 31;
        float val = s_qq[(r >> 1) * SQ + (r & 1) * 130 + e];
        outC[(((size_t)b * E_ + e) * H_ + h) * (size_t)L_ + l0 + r] = val;
    }
}

extern "C" void kernel_launch(void* const* d_in, const int* in_sizes, int n_in,
                              void* d_out, int out_size)
{
    const float* Q = (const float*)d_in[0];
    const float* K = (const float*)d_in[1];
    const float* V = (const float*)d_in[2];
    float* outV = (float*)d_out;
    float* outC = outV + (size_t)B_ * H_ * L_ * E_;

    dim3 grid(L_ / ROWS, B_ * H_);
    ac_kernel<<<grid, NTHREADS>>>(Q, K, V, outV, outC);
}

// round 5
// speedup vs baseline: 1.1942x; 1.1557x over previous
#include <cuda_runtime.h>
#include <math_constants.h>

#define B_ 32
#define H_ 8
#define L_ 2048
#define E_ 64

#define NTHREADS 128
#define ROWS 32          // rows per block
#define RPC  16          // row-pairs per block
#define SQ 260           // q region stride per rp (256 dup-interleaved words + pad); corr staging aliases
#define SK 132           // k region stride (33 chunks == 1 mod 8 -> LDK broadcast spread)
#define SV 140           // v row stride (128 dup words + pad; 140 mod 32 = 12 spreads gather)

// chunk swizzle: conflict-free for both store pattern (8g+4par+u) and FIR octet pattern (C+4s)
__device__ __forceinline__ int sw(int c) { return c ^ ((c >> 2) & 7); }

// packed f32x2 fma: d = a*b + d (lo = even row, hi = odd row)
__device__ __forceinline__ void ffma2(unsigned long long& d,
                                      unsigned long long a,
                                      unsigned long long b) {
    asm("fma.rn.f32x2 %0, %1, %2, %0;" : "+l"(d) : "l"(a), "l"(b));
}

// AutoCorrelation (Autoformer):
//   corr[b,h,l,d] = sum_e q[b,h,l,(e+d)%64] * k[b,h,l,e]
//   top-4 over d, softmax, V_out[e] = sum_i p_i * v[(e+d_i)%64]
//   outputs: V (B,H,L,E) then corr transposed to (B,E,H,L)
__global__ __launch_bounds__(NTHREADS, 5)
void ac_kernel(const float* __restrict__ Q, const float* __restrict__ Kk,
               const float* __restrict__ Vv, float* __restrict__ outV,
               float* __restrict__ outC)
{
    __shared__ __align__(16) float s_qq[RPC * SQ];   // interleaved (even,odd) q pairs, dup, swizzled
    __shared__ __align__(16) float s_kk[RPC * SK];   // interleaved k pairs, swizzled
    __shared__ __align__(16) float s_v [ROWS * SV];  // v duplicated, plain

    const int t     = threadIdx.x;
    const int lane  = t & 31;
    const int w     = t >> 5;
    const int ltile = blockIdx.x;
    const int bh    = blockIdx.y;
    const int h     = bh & (H_ - 1);
    const int b     = bh >> 3;
    const int l0    = ltile * ROWS;

    // ---------------- load phase: warp owns rows 8w..8w+7 --------------------
    {
        const int g   = lane & 3;          // 4 col-groups of 16 floats
        const int rr  = lane >> 2;         // 8 local rows per warp
        const int par = rr & 1;
        const int rl  = 8 * w + rr;
        const int rpg = rl >> 1;
        const size_t rowbase = ((size_t)bh * L_ + l0 + rl) * (size_t)E_;
        const int col = 16 * g;

        float qa[16], ka[16], va[16];
        #pragma unroll
        for (int u = 0; u < 4; ++u) {
            *(float4*)(qa + 4*u) = *(const float4*)(Q  + rowbase + col + 4*u);
            *(float4*)(ka + 4*u) = *(const float4*)(Kk + rowbase + col + 4*u);
            *(float4*)(va + 4*u) = *(const float4*)(Vv + rowbase + col + 4*u);
        }

        // v: plain + duplicate
        float* vr = s_v + rl * SV;
        #pragma unroll
        for (int u = 0; u < 4; ++u) {
            *(float4*)(vr + col + 4*u)      = *(float4*)(va + 4*u);
            *(float4*)(vr + col + 4*u + 64) = *(float4*)(va + 4*u);
        }

        // parity exchange (lane^4 = other row of same pair, same col-group):
        // par0 sends its high 8 cols, par1 sends its low 8 cols
        float qr[8], kr[8];
        #pragma unroll
        for (int j = 0; j < 8; ++j) {
            float qs = par ? qa[j] : qa[8 + j];
            float ks = par ? ka[j] : ka[8 + j];
            qr[j] = __shfl_xor_sync(0xffffffffu, qs, 4);
            kr[j] = __shfl_xor_sync(0xffffffffu, ks, 4);
        }

        float* qrow = s_qq + rpg * SQ;
        float* krow = s_kk + rpg * SK;
        #pragma unroll
        for (int u = 0; u < 4; ++u) {
            const int c   = 8*g + 4*par + u;       // logical chunk (2 element-pairs)
            const int off = 4 * sw(c);
            float4 fq, fk;
            if (!par) {   // pairs for cols col..col+7: (even=mine, odd=partner)
                fq = make_float4(qa[2*u], qr[2*u], qa[2*u+1], qr[2*u+1]);
                fk = make_float4(ka[2*u], kr[2*u], ka[2*u+1], kr[2*u+1]);
            } else {      // pairs for cols col+8..col+15: (even=partner, odd=mine)
                fq = make_float4(qr[2*u], qa[8+2*u], qr[2*u+1], qa[8+2*u+1]);
                fk = make_float4(kr[2*u], ka[8+2*u], kr[2*u+1], ka[8+2*u+1]);
            }
            *(float4*)(qrow + off)       = fq;
            *(float4*)(qrow + off + 128) = fq;     // duplicate: sw(c+32) == sw(c)+32
            *(float4*)(krow + off)       = fk;
        }
    }
    __syncwarp();

    // ---------------- FIR correlation: 8 delays/lane, f32x2, 2 rows/lane -----
    const int s   = lane & 7;            // delay-octet sub-lane
    const int oct = lane >> 3;
    const int rp  = 4 * w + oct;         // row-pair owned by this octet
    const float* qq = s_qq + rp * SQ;
    const float* kk = s_kk + rp * SK;
    const int cb0 = 4 * s;               // chunk of element d0 = 8s

    unsigned long long W[12], acc[8];
    #pragma unroll
    for (int u = 0; u < 4; ++u) {
        ulonglong2 tv = *(const ulonglong2*)(qq + 4 * sw(cb0 + u));
        W[2*u] = tv.x; W[2*u + 1] = tv.y;
    }
    #pragma unroll
    for (int j = 0; j < 8; ++j) acc[j] = 0ull;

    #pragma unroll
    for (int blk = 0; blk < 16; ++blk) {
        ulonglong2 t0 = *(const ulonglong2*)(qq + 4 * sw(cb0 + 2*blk + 4));
        ulonglong2 t1 = *(const ulonglong2*)(qq + 4 * sw(cb0 + 2*blk + 5));
        W[8] = t0.x; W[9] = t0.y; W[10] = t1.x; W[11] = t1.y;
        ulonglong2 ka_ = *(const ulonglong2*)(kk + 4 * sw(2*blk));      // consts: folded
        ulonglong2 kb_ = *(const ulonglong2*)(kk + 4 * sw(2*blk + 1));
        unsigned long long kp[4] = {ka_.x, ka_.y, kb_.x, kb_.y};
        #pragma unroll
        for (int tt = 0; tt < 4; ++tt)
            #pragma unroll
            for (int j = 0; j < 8; ++j)
                ffma2(acc[j], W[tt + j], kp[tt]);
        #pragma unroll
        for (int m = 0; m < 8; ++m) W[m] = W[m + 4];
    }
    __syncwarp();   // all q reads done before aliased corr staging

    // ---------------- split accumulators; stage corr into aliased q region ---
    float ex[8], od[8];
    #pragma unroll
    for (int j = 0; j < 8; ++j) {
        float2 f = *reinterpret_cast<float2*>(&acc[j]);
        ex[j] = f.x; od[j] = f.y;
    }
    {
        float* ce = s_qq + rp * SQ;      // corr row 2rp   : words 0..63
        float* co = ce + 130;            // corr row 2rp+1 : words 130..193 (8B aligned)
        *(float4*)(ce + 8*s)     = make_float4(ex[0], ex[1], ex[2], ex[3]);
        *(float4*)(ce + 8*s + 4) = make_float4(ex[4], ex[5], ex[6], ex[7]);
        *(float2*)(co + 8*s)     = make_float2(od[0], od[1]);
        *(float2*)(co + 8*s + 2) = make_float2(od[2], od[3]);
        *(float2*)(co + 8*s + 4) = make_float2(od[4], od[5]);
        *(float2*)(co + 8*s + 6) = make_float2(od[6], od[7]);
    }

    // ---------------- top-4 + softmax + gather (register candidates) ---------
    #pragma unroll
    for (int pass = 0; pass < 2; ++pass) {
        const int rowl = 8 * w + 2 * oct + pass;
        float av[8];
        #pragma unroll
        for (int j = 0; j < 8; ++j) av[j] = pass ? od[j] : ex[j];

        float wv[4]; int wd[4];
        #pragma unroll
        for (int i = 0; i < 4; ++i) {
            // local argmax over 8 regs, lowest index wins ties
            float bv = av[0]; int bj = 0;
            #pragma unroll
            for (int j = 1; j < 8; ++j)
                if (av[j] > bv) { bv = av[j]; bj = j; }
            int bi = 8 * s + bj;
            // 8-lane butterfly within octet, lexicographic (val desc, idx asc)
            #pragma unroll
            for (int off = 4; off; off >>= 1) {
                float ov = __shfl_xor_sync(0xffffffffu, bv, off);
                int   oi = __shfl_xor_sync(0xffffffffu, bi, off);
                if (ov > bv || (ov == bv && oi < bi)) { bv = ov; bi = oi; }
            }
            wv[i] = bv; wd[i] = bi;
            if (i < 3 && (bi >> 3) == s) {        // owner removes selected slot
                const int jb = bi & 7;
                #pragma unroll
                for (int j = 0; j < 8; ++j)
                    if (j == jb) av[j] = -CUDART_INF_F;
            }
        }

        float p[4]; float z = 0.f;
        #pragma unroll
        for (int i = 0; i < 4; ++i) { p[i] = __expf(wv[i] - wv[0]); z += p[i]; }
        const float rz = 1.f / z;

        // gather from duplicated v: index s + 8m + d <= 126 < 128
        const float* vrow = s_v + rowl * SV;
        float om[8] = {0.f,0.f,0.f,0.f,0.f,0.f,0.f,0.f};
        #pragma unroll
        for (int i = 0; i < 4; ++i) {
            const float pi = p[i] * rz;
            const int base = s + wd[i];
            #pragma unroll
            for (int m = 0; m < 8; ++m)
                om[m] = fmaf(pi, vrow[base + 8*m], om[m]);
        }
        const size_t vb = ((size_t)bh * L_ + l0 + rowl) * (size_t)E_;
        #pragma unroll
        for (int m = 0; m < 8; ++m)
            outV[vb + s + 8*m] = om[m];
    }

    // ---------------- transposed corr write: outC[b,e,h,l] -------------------
    __syncthreads();
    #pragma unroll
    for (int idx = t; idx < E_ * ROWS; idx += NTHREADS) {
        int e = idx >> 5;            // ROWS == 32
        int r = idx & 31;
        float val = s_qq[(r >> 1) * SQ + (r & 1) * 130 + e];
        outC[(((size_t)b * E_ + e) * H_ + h) * (size_t)L_ + l0 + r] = val;
    }
}

extern "C" void kernel_launch(void* const* d_in, const int* in_sizes, int n_in,
                              void* d_out, int out_size)
{
    const float* Q = (const float*)d_in[0];
    const float* K = (const float*)d_in[1];
    const float* V = (const float*)d_in[2];
    float* outV = (float*)d_out;
    float* outC = outV + (size_t)B_ * H_ * L_ * E_;

    dim3 grid(L_ / ROWS, B_ * H_);
    ac_kernel<<<grid, NTHREADS>>>(Q, K, V, outV, outC);
}